// round 2
// baseline (speedup 1.0000x reference)
#include <cuda_runtime.h>
#include <cuda_bf16.h>

// ---------------------------------------------------------------------------
// SigTKANDense: tw*x -> depth-2 signature -> GRKAN (softmax weights) ->
//               big KAN-linear over (B*S) rows -> scale by weights.
// B=64, S=1024, D=64, U=128, NB=8, SIG_DIM=4160.
// ---------------------------------------------------------------------------

#define NB_ 8
#define B_ 64
#define S_ 1024
#define D_ 64
#define U_ 128
#define SIGD_ 4160
#define NCHUNK_ 130   // 4160/32 feature chunks for GRKAN stage 1

// scratch (no allocations allowed -> device globals)
__device__ float g_sig[B_ * SIGD_];                  // [b][4160]
__device__ float g_part[NCHUNK_ * B_ * 256];         // [chunk][b][0:128]=h1, [128:256]=skip
__device__ float g_weights[B_ * U_];                 // softmax weights per batch

// ---------------------------------------------------------------------------
// cubic B-spline, 12 uniform knots on [-2.2, 2.2], 8 bases out
// ---------------------------------------------------------------------------
__device__ __forceinline__ void bspline8(float x, float* bs) {
    float b[11];
#pragma unroll
    for (int i = 0; i < 11; i++) {
        float g0 = (float)((i - 3) * 0.4 - 1.0);
        float g1 = (float)((i - 2) * 0.4 - 1.0);
        b[i] = (x >= g0 && x < g1) ? 1.0f : 0.0f;
    }
#pragma unroll
    for (int p = 1; p <= 3; p++) {
        float inv = (float)(1.0 / (0.4 * p));
#pragma unroll
        for (int i = 0; i < 11 - p; i++) {
            float gi  = (float)((i - 3) * 0.4 - 1.0);       // grid[i]
            float gip = (float)((i + p - 2) * 0.4 - 1.0);   // grid[i+p+1]
            b[i] = ((x - gi) * b[i] + (gip - x) * b[i + 1]) * inv;
        }
    }
#pragma unroll
    for (int j = 0; j < 8; j++) bs[j] = b[j];
}

__device__ __forceinline__ float silu_f(float x) {
    return x * (1.0f / (1.0f + __expf(-x)));
}

// packed f32x2 helpers (Blackwell 2x fp32 pipe)
__device__ __forceinline__ unsigned long long pack2(float v) {
    unsigned long long r;
    asm("mov.b64 %0, {%1, %1};" : "=l"(r) : "f"(v));
    return r;
}
__device__ __forceinline__ unsigned long long ff2(unsigned long long a,
                                                  unsigned long long b,
                                                  unsigned long long c) {
    unsigned long long d;
    asm("fma.rn.f32x2 %0, %1, %2, %3;" : "=l"(d) : "l"(a), "l"(b), "l"(c));
    return d;
}
__device__ __forceinline__ void unpack2(unsigned long long a, float& lo, float& hi) {
    asm("mov.b64 {%0, %1}, %2;" : "=f"(lo), "=f"(hi) : "l"(a));
}

// ---------------------------------------------------------------------------
// K0: zero the signature accumulator
// ---------------------------------------------------------------------------
__global__ void zero_sig_kernel() {
    int i = blockIdx.x * blockDim.x + threadIdx.x;
    if (i < B_ * SIGD_) g_sig[i] = 0.0f;
}

// ---------------------------------------------------------------------------
// K1: depth-2 signature.
//   S1[i]    = w[S-1][i] - w[0][i]
//   S2[i][j] = sum_t (0.5*(w_t+w_{t+1})[i] - w_0[i]) * (w_{t+1}-w_t)[j]
// grid (64 batches, 8 t-chunks of 128 steps), 256 threads, 4x4 reg tiles.
// ---------------------------------------------------------------------------
__global__ void __launch_bounds__(256) sig_kernel(const float* __restrict__ x,
                                                  const float* __restrict__ tw) {
    int b = blockIdx.x;
    int chunk = blockIdx.y;
    int t0 = chunk * 128;
    int t1 = min(1023, t0 + 128);
    int nt = t1 - t0;                      // steps in this chunk
    __shared__ float rows[129 * 64];
    __shared__ float w0s[64];
    __shared__ float cu[2048];             // c[16][64] then u[16][64]
    int tid = threadIdx.x;

    if (tid < 64) w0s[tid] = tw[0] * x[(size_t)(b * S_) * D_ + tid];
    for (int idx = tid; idx < (nt + 1) * 64; idx += 256) {
        int r = idx >> 6, d = idx & 63;
        rows[idx] = tw[t0 + r] * x[(size_t)(b * S_ + t0 + r) * D_ + d];
    }
    __syncthreads();

    float acc[4][4];
#pragma unroll
    for (int a = 0; a < 4; a++)
#pragma unroll
        for (int e = 0; e < 4; e++) acc[a][e] = 0.0f;

    int tj = (tid & 15) * 4;
    int ti = (tid >> 4) * 4;

    for (int tb = 0; tb < nt; tb += 16) {
        int m = min(16, nt - tb);
        for (int idx = tid; idx < m * 64; idx += 256) {
            int lt = idx >> 6, d = idx & 63;
            float r0 = rows[(tb + lt) * 64 + d];
            float r1 = rows[(tb + lt + 1) * 64 + d];
            cu[lt * 64 + d] = 0.5f * (r0 + r1) - w0s[d];   // c
            cu[1024 + lt * 64 + d] = r1 - r0;              // u
        }
        __syncthreads();
        for (int lt = 0; lt < m; lt++) {
            float4 ci = *(const float4*)&cu[lt * 64 + ti];
            float4 uj = *(const float4*)&cu[1024 + lt * 64 + tj];
            float c[4] = {ci.x, ci.y, ci.z, ci.w};
            float u[4] = {uj.x, uj.y, uj.z, uj.w};
#pragma unroll
            for (int a = 0; a < 4; a++)
#pragma unroll
                for (int e = 0; e < 4; e++) acc[a][e] = fmaf(c[a], u[e], acc[a][e]);
        }
        __syncthreads();
    }

    float* s2 = g_sig + (size_t)b * SIGD_ + 64;
#pragma unroll
    for (int a = 0; a < 4; a++)
#pragma unroll
        for (int e = 0; e < 4; e++)
            atomicAdd(&s2[(ti + a) * 64 + (tj + e)], acc[a][e]);

    if (chunk == 0 && tid < 64) {
        g_sig[(size_t)b * SIGD_ + tid] =
            tw[1023] * x[(size_t)(b * S_ + 1023) * D_ + tid] - w0s[tid];
    }
}

// ---------------------------------------------------------------------------
// K2: GRKAN stage 1: partial h1 = kan_linear(sig, g1_*) and partial skip =
// sig @ skip_w, chunked over features (32 per CTA). Weight matrices streamed
// exactly once. Partials -> g_part (reduced in K3).
// ---------------------------------------------------------------------------
__global__ void __launch_bounds__(256) grkan1_kernel(const float* __restrict__ g1_base,
                                                     const float* __restrict__ g1_spline,
                                                     const float* __restrict__ skip_w) {
    int cta = blockIdx.x;           // 0..129
    int f0 = cta * 32;
    int tid = threadIdx.x;
    __shared__ float sig_s[64 * 32];        // [b][f_local]
    __shared__ float feats[8 * 64 * 12];    // [f_sub][b][silu, b0..b7, raw, pad, pad]

    for (int idx = tid; idx < 64 * 32; idx += 256) {
        int bb = idx >> 5, fl = idx & 31;
        sig_s[idx] = g_sig[(size_t)bb * SIGD_ + f0 + fl];
    }

    float acc[64];
#pragma unroll
    for (int i = 0; i < 64; i++) acc[i] = 0.0f;

    for (int g = 0; g < 4; g++) {
        __syncthreads();   // protects sig_s (g=0) and feats reuse
        // phase 1: bases for 8 features x 64 batch rows (512 tasks / 256 thr)
#pragma unroll
        for (int k = 0; k < 2; k++) {
            int task = tid + k * 256;
            int fg = task & 7, bb = task >> 3;
            float s = sig_s[bb * 32 + g * 8 + fg];
            float* fp = &feats[(fg * 64 + bb) * 12];
            fp[0] = silu_f(s);
            float bsv[8];
            bspline8(s, bsv);
#pragma unroll
            for (int j = 0; j < 8; j++) fp[1 + j] = bsv[j];
            fp[9] = s;
        }
        __syncthreads();
        // phase 2
        if (tid < 128) {
            int u = tid;
            for (int fg = 0; fg < 8; fg++) {
                int f = f0 + g * 8 + fg;
                float wb  = g1_base[(size_t)f * U_ + u];
                float ws0 = g1_spline[(size_t)(f * 8 + 0) * U_ + u];
                float ws1 = g1_spline[(size_t)(f * 8 + 1) * U_ + u];
                float ws2 = g1_spline[(size_t)(f * 8 + 2) * U_ + u];
                float ws3 = g1_spline[(size_t)(f * 8 + 3) * U_ + u];
                float ws4 = g1_spline[(size_t)(f * 8 + 4) * U_ + u];
                float ws5 = g1_spline[(size_t)(f * 8 + 5) * U_ + u];
                float ws6 = g1_spline[(size_t)(f * 8 + 6) * U_ + u];
                float ws7 = g1_spline[(size_t)(f * 8 + 7) * U_ + u];
#pragma unroll
                for (int bb = 0; bb < 64; bb++) {
                    const float* fp = &feats[(fg * 64 + bb) * 12];
                    float4 v0 = *(const float4*)(fp);
                    float4 v1 = *(const float4*)(fp + 4);
                    float  v2 = fp[8];
                    float t = v0.x * wb;
                    t = fmaf(v0.y, ws0, t);
                    t = fmaf(v0.z, ws1, t);
                    t = fmaf(v0.w, ws2, t);
                    t = fmaf(v1.x, ws3, t);
                    t = fmaf(v1.y, ws4, t);
                    t = fmaf(v1.z, ws5, t);
                    t = fmaf(v1.w, ws6, t);
                    t = fmaf(v2,   ws7, t);
                    acc[bb] += t;
                }
            }
        } else {
            int u = tid - 128;
            for (int fg = 0; fg < 8; fg++) {
                int f = f0 + g * 8 + fg;
                float wk = skip_w[(size_t)f * U_ + u];
#pragma unroll
                for (int bb = 0; bb < 64; bb++) {
                    acc[bb] = fmaf(feats[(fg * 64 + bb) * 12 + 9], wk, acc[bb]);
                }
            }
        }
    }
    size_t base = (size_t)cta * 64 * 256;
#pragma unroll
    for (int bb = 0; bb < 64; bb++) g_part[base + bb * 256 + tid] = acc[bb];
}

// ---------------------------------------------------------------------------
// K3: GRKAN tail per batch row: reduce partials, kan_linear #2, gate,
// layernorm, softmax -> g_weights. 64 CTAs x 128 threads.
// ---------------------------------------------------------------------------
__global__ void __launch_bounds__(128) grkan2_kernel(const float* __restrict__ g2_base,
                                                     const float* __restrict__ g2_spline,
                                                     const float* __restrict__ skip_b,
                                                     const float* __restrict__ gate_ws,
                                                     const float* __restrict__ gate_bs,
                                                     const float* __restrict__ gate_wv,
                                                     const float* __restrict__ gate_bv,
                                                     const float* __restrict__ ln_g,
                                                     const float* __restrict__ ln_b) {
    int b = blockIdx.x;
    int u = threadIdx.x;
    __shared__ float s_feats[9][128];
    __shared__ float s_h2[128];
    __shared__ float red[16];

    float h1v = 0.0f, skv = 0.0f;
    for (int c = 0; c < NCHUNK_; c++) {
        const float* p = g_part + ((size_t)c * 64 + b) * 256;
        h1v += p[u];
        skv += p[128 + u];
    }

    {
        s_feats[0][u] = silu_f(h1v);
        float bsv[8];
        bspline8(h1v, bsv);
#pragma unroll
        for (int j = 0; j < 8; j++) s_feats[1 + j][u] = bsv[j];
    }
    __syncthreads();

    float h2 = 0.0f;
    for (int f = 0; f < 128; f++) {
        float t = s_feats[0][f] * g2_base[(size_t)f * U_ + u];
#pragma unroll
        for (int j = 0; j < 8; j++)
            t = fmaf(s_feats[1 + j][f], g2_spline[(size_t)(f * 8 + j) * U_ + u], t);
        h2 += t;
    }
    s_h2[u] = h2;
    __syncthreads();

    float gs = gate_bs[u], gv = gate_bv[u];
    for (int f = 0; f < 128; f++) {
        float h = s_h2[f];
        gs = fmaf(h, gate_ws[(size_t)f * U_ + u], gs);
        gv = fmaf(h, gate_wv[(size_t)f * U_ + u], gv);
    }
    float pre = skv + skip_b[u] + (1.0f / (1.0f + __expf(-gs))) * gv;

    // layernorm (eps = 1e-3, population var)
    float v1 = pre, v2 = pre * pre;
#pragma unroll
    for (int o = 16; o; o >>= 1) {
        v1 += __shfl_xor_sync(0xffffffffu, v1, o);
        v2 += __shfl_xor_sync(0xffffffffu, v2, o);
    }
    int w = u >> 5, l = u & 31;
    if (l == 0) { red[w] = v1; red[4 + w] = v2; }
    __syncthreads();
    float mean = (red[0] + red[1] + red[2] + red[3]) * (1.0f / 128.0f);
    float ms   = (red[4] + red[5] + red[6] + red[7]) * (1.0f / 128.0f);
    float var  = ms - mean * mean;
    float ln   = ln_g[u] * (pre - mean) * rsqrtf(var + 1e-3f) + ln_b[u];

    // softmax
    float m = ln;
#pragma unroll
    for (int o = 16; o; o >>= 1) m = fmaxf(m, __shfl_xor_sync(0xffffffffu, m, o));
    if (l == 0) red[8 + w] = m;
    __syncthreads();
    m = fmaxf(fmaxf(red[8], red[9]), fmaxf(red[10], red[11]));
    float e = __expf(ln - m);
    float se = e;
#pragma unroll
    for (int o = 16; o; o >>= 1) se += __shfl_xor_sync(0xffffffffu, se, o);
    if (l == 0) red[12 + w] = se;
    __syncthreads();
    se = red[12] + red[13] + red[14] + red[15];

    g_weights[b * U_ + u] = e / se;
}

// ---------------------------------------------------------------------------
// K4: main fused KAN layer over all B*S rows, f32x2 packed math.
// CTA = 64 rows (one batch, contiguous s) x 128 output cols (thread = u).
// acc[pair] holds rows (2p, 2p+1) packed in b64; weights dup-packed.
// ---------------------------------------------------------------------------
__global__ void __launch_bounds__(128) main_kernel(const float* __restrict__ x,
                                                   const float* __restrict__ tw,
                                                   const float* __restrict__ kan_base,
                                                   const float* __restrict__ kan_spline,
                                                   float* __restrict__ out) {
    int cta = blockIdx.x;            // 1024 CTAs
    int b = cta >> 4;
    int s0 = (cta & 15) << 6;
    int tid = threadIdx.x;           // = output u
    __shared__ float xt[64 * 65];    // padded: avoid column-read conflicts
    __shared__ float sf[2 * 9 * 64]; // [p][j][row]

    for (int idx = tid; idx < 64 * 64; idx += 128) {
        int r = idx >> 6, d = idx & 63;
        xt[r * 65 + d] = tw[s0 + r] * x[(size_t)(b * S_ + s0 + r) * D_ + d];
    }

    unsigned long long acc[32];
#pragma unroll
    for (int i = 0; i < 32; i++) acc[i] = 0ull;

    for (int f = 0; f < 64; f += 2) {
        __syncthreads();   // covers xt load (f=0) and sf reuse
        {
            int p = tid >> 6, r = tid & 63;
            float v = xt[r * 65 + f + p];
            float* sp = &sf[p * 9 * 64];
            sp[r] = silu_f(v);
            float bsv[8];
            bspline8(v, bsv);
#pragma unroll
            for (int j = 0; j < 8; j++) sp[(1 + j) * 64 + r] = bsv[j];
        }
        __syncthreads();
#pragma unroll
        for (int p = 0; p < 2; p++) {
            unsigned long long wd[9];
            wd[0] = pack2(kan_base[(size_t)(f + p) * U_ + tid]);
#pragma unroll
            for (int j = 0; j < 8; j++)
                wd[1 + j] = pack2(kan_spline[(size_t)((f + p) * 8 + j) * U_ + tid]);
            const float* sp = &sf[p * 9 * 64];
#pragma unroll
            for (int pr = 0; pr < 32; pr++) {
#pragma unroll
                for (int j = 0; j < 9; j++) {
                    unsigned long long v =
                        *(const unsigned long long*)&sp[j * 64 + 2 * pr];
                    acc[pr] = ff2(v, wd[j], acc[pr]);
                }
            }
        }
    }

    float wgt = g_weights[b * U_ + tid];
    size_t obase = (size_t)(b * S_ + s0) * U_ + tid;
#pragma unroll
    for (int pr = 0; pr < 32; pr++) {
        float lo, hi;
        unpack2(acc[pr], lo, hi);
        out[obase + (size_t)(2 * pr) * U_]     = lo * wgt;
        out[obase + (size_t)(2 * pr + 1) * U_] = hi * wgt;
    }
}

// ---------------------------------------------------------------------------
extern "C" void kernel_launch(void* const* d_in, const int* in_sizes, int n_in,
                              void* d_out, int out_size) {
    const float* x          = (const float*)d_in[0];
    const float* tw         = (const float*)d_in[1];
    const float* kan_base   = (const float*)d_in[2];
    const float* kan_spline = (const float*)d_in[3];
    const float* g1_base    = (const float*)d_in[4];
    const float* g1_spline  = (const float*)d_in[5];
    const float* g2_base    = (const float*)d_in[6];
    const float* g2_spline  = (const float*)d_in[7];
    const float* skip_w     = (const float*)d_in[8];
    const float* skip_b     = (const float*)d_in[9];
    const float* gate_ws    = (const float*)d_in[10];
    const float* gate_bs    = (const float*)d_in[11];
    const float* gate_wv    = (const float*)d_in[12];
    const float* gate_bv    = (const float*)d_in[13];
    const float* ln_g       = (const float*)d_in[14];
    const float* ln_b       = (const float*)d_in[15];
    float* out = (float*)d_out;

    zero_sig_kernel<<<(B_ * SIGD_ + 255) / 256, 256>>>();
    sig_kernel<<<dim3(B_, 8), 256>>>(x, tw);
    grkan1_kernel<<<NCHUNK_, 256>>>(g1_base, g1_spline, skip_w);
    grkan2_kernel<<<B_, 128>>>(g2_base, g2_spline, skip_b, gate_ws, gate_bs,
                               gate_wv, gate_bv, ln_g, ln_b);
    main_kernel<<<1024, 128>>>(x, tw, kan_base, kan_spline, out);
}

// round 6
// speedup vs baseline: 1.6548x; 1.6548x over previous
#include <cuda_runtime.h>
#include <cuda_bf16.h>

// ---------------------------------------------------------------------------
// SigTKANDense: tw*x -> depth-2 signature -> GRKAN (softmax weights) ->
//               big KAN-linear over (B*S) rows -> scale by weights.
// B=64, S=1024, D=64, U=128, NB=8, SIG_DIM=4160.
// ---------------------------------------------------------------------------

#define NB_ 8
#define B_ 64
#define S_ 1024
#define D_ 64
#define U_ 128
#define SIGD_ 4160
#define NCHUNK_ 130   // 4160/32 feature chunks

typedef unsigned long long ull;

// scratch (no allocations allowed -> device globals)
__device__ float g_sig[B_ * SIGD_];            // [b][4160]
__device__ float g_part[NCHUNK_ * B_ * U_];    // h1 partials [chunk][b][u]
__device__ float g_skip[B_ * U_];              // skip accumulator (atomics)
__device__ float g_h2[B_ * U_];                // h2 accumulator (atomics)
__device__ float g_feat1[B_ * 9 * U_];         // features of h1: [b][j][u]
__device__ float g_weights[B_ * U_];           // softmax weights per batch

// ---------------------------------------------------------------------------
// cubic B-spline, 12 uniform knots, 8 bases out
// ---------------------------------------------------------------------------
__device__ __forceinline__ void bspline8(float x, float* bs) {
    float b[11];
#pragma unroll
    for (int i = 0; i < 11; i++) {
        float g0 = (float)((i - 3) * 0.4 - 1.0);
        float g1 = (float)((i - 2) * 0.4 - 1.0);
        b[i] = (x >= g0 && x < g1) ? 1.0f : 0.0f;
    }
#pragma unroll
    for (int p = 1; p <= 3; p++) {
        float inv = (float)(1.0 / (0.4 * p));
#pragma unroll
        for (int i = 0; i < 11 - p; i++) {
            float gi  = (float)((i - 3) * 0.4 - 1.0);       // grid[i]
            float gip = (float)((i + p - 2) * 0.4 - 1.0);   // grid[i+p+1]
            b[i] = ((x - gi) * b[i] + (gip - x) * b[i + 1]) * inv;
        }
    }
#pragma unroll
    for (int j = 0; j < 8; j++) bs[j] = b[j];
}

__device__ __forceinline__ float silu_f(float x) {
    return x * (1.0f / (1.0f + __expf(-x)));
}

__device__ __forceinline__ ull ff2(ull a, ull b, ull c) {
    ull d;
    asm("fma.rn.f32x2 %0, %1, %2, %3;" : "=l"(d) : "l"(a), "l"(b), "l"(c));
    return d;
}
__device__ __forceinline__ void unpack2(ull a, float& lo, float& hi) {
    asm("mov.b64 {%0, %1}, %2;" : "=f"(lo), "=f"(hi) : "l"(a));
}

// ---------------------------------------------------------------------------
// K0: zero the accumulators (g_sig, g_skip, g_h2)
// ---------------------------------------------------------------------------
#define ZTOT_ (B_ * SIGD_ + 2 * B_ * U_)
__global__ void zero_kernel() {
    int i = blockIdx.x * blockDim.x + threadIdx.x;
    if (i < B_ * SIGD_) g_sig[i] = 0.0f;
    else if (i < B_ * SIGD_ + B_ * U_) g_skip[i - B_ * SIGD_] = 0.0f;
    else if (i < ZTOT_) g_h2[i - B_ * SIGD_ - B_ * U_] = 0.0f;
}

// ---------------------------------------------------------------------------
// K1: depth-2 signature.
//   S1[i]    = w[S-1][i] - w[0][i]
//   S2[i][j] = sum_t (0.5*(w_t+w_{t+1})[i] - w_0[i]) * (w_{t+1}-w_t)[j]
// ---------------------------------------------------------------------------
__global__ void __launch_bounds__(256) sig_kernel(const float* __restrict__ x,
                                                  const float* __restrict__ tw) {
    int b = blockIdx.x;
    int chunk = blockIdx.y;
    int t0 = chunk * 128;
    int t1 = min(1023, t0 + 128);
    int nt = t1 - t0;
    __shared__ float rows[129 * 64];
    __shared__ float w0s[64];
    __shared__ float cu[2048];
    int tid = threadIdx.x;

    if (tid < 64) w0s[tid] = tw[0] * x[(size_t)(b * S_) * D_ + tid];
    for (int idx = tid; idx < (nt + 1) * 64; idx += 256) {
        int r = idx >> 6, d = idx & 63;
        rows[idx] = tw[t0 + r] * x[(size_t)(b * S_ + t0 + r) * D_ + d];
    }
    __syncthreads();

    float acc[4][4];
#pragma unroll
    for (int a = 0; a < 4; a++)
#pragma unroll
        for (int e = 0; e < 4; e++) acc[a][e] = 0.0f;

    int tj = (tid & 15) * 4;
    int ti = (tid >> 4) * 4;

    for (int tb = 0; tb < nt; tb += 16) {
        int m = min(16, nt - tb);
        for (int idx = tid; idx < m * 64; idx += 256) {
            int lt = idx >> 6, d = idx & 63;
            float r0 = rows[(tb + lt) * 64 + d];
            float r1 = rows[(tb + lt + 1) * 64 + d];
            cu[lt * 64 + d] = 0.5f * (r0 + r1) - w0s[d];
            cu[1024 + lt * 64 + d] = r1 - r0;
        }
        __syncthreads();
        for (int lt = 0; lt < m; lt++) {
            float4 ci = *(const float4*)&cu[lt * 64 + ti];
            float4 uj = *(const float4*)&cu[1024 + lt * 64 + tj];
            float c[4] = {ci.x, ci.y, ci.z, ci.w};
            float u[4] = {uj.x, uj.y, uj.z, uj.w};
#pragma unroll
            for (int a = 0; a < 4; a++)
#pragma unroll
                for (int e = 0; e < 4; e++) acc[a][e] = fmaf(c[a], u[e], acc[a][e]);
        }
        __syncthreads();
    }

    float* s2 = g_sig + (size_t)b * SIGD_ + 64;
#pragma unroll
    for (int a = 0; a < 4; a++)
#pragma unroll
        for (int e = 0; e < 4; e++)
            atomicAdd(&s2[(ti + a) * 64 + (tj + e)], acc[a][e]);

    if (chunk == 0 && tid < 64) {
        g_sig[(size_t)b * SIGD_ + tid] =
            tw[1023] * x[(size_t)(b * S_ + 1023) * D_ + tid] - w0s[tid];
    }
}

// ---------------------------------------------------------------------------
// K2: GRKAN stage-1 h1 partials, column-pair f32x2 scheme.
// CTA = 32 features x 64 b-rows x 128 u-cols. 128 threads:
//   cg = tid&15 (8 cols each, as 4 b64 pairs), rg = tid>>4 (8 rows each).
// Features stored DUPLICATED (float2{v,v}) so LDS.64 gives a packed dup;
// weight b64 pairs come straight from LDG.128 (no packing movs).
// ---------------------------------------------------------------------------
__global__ void __launch_bounds__(128) grkan1_kernel(const float* __restrict__ g1_base,
                                                     const float* __restrict__ g1_spline) {
    int cta = blockIdx.x;           // 0..129
    int f0 = cta * 32;
    int tid = threadIdx.x;
    int cg = tid & 15, rg = tid >> 4;
    __shared__ float sig_s[64][32];
    __shared__ float2 featsd[2][9][64];

    for (int idx = tid; idx < 64 * 32; idx += 128) {
        int bb = idx >> 5, fl = idx & 31;
        sig_s[bb][fl] = g_sig[(size_t)bb * SIGD_ + f0 + fl];
    }

    ull acc[8][4];
#pragma unroll
    for (int r = 0; r < 8; r++)
#pragma unroll
        for (int c = 0; c < 4; c++) acc[r][c] = 0ull;

    for (int f = 0; f < 32; f += 2) {
        __syncthreads();
        {
            int p = tid >> 6, bb = tid & 63;
            float v = sig_s[bb][f + p];
            float sv = silu_f(v);
            featsd[p][0][bb] = make_float2(sv, sv);
            float bsv[8];
            bspline8(v, bsv);
#pragma unroll
            for (int j = 0; j < 8; j++)
                featsd[p][1 + j][bb] = make_float2(bsv[j], bsv[j]);
        }
        __syncthreads();
#pragma unroll
        for (int p = 0; p < 2; p++) {
            int ff = f0 + f + p;
#pragma unroll
            for (int j = 0; j < 9; j++) {
                const float* wrow = (j == 0) ? (g1_base + (size_t)ff * U_)
                                             : (g1_spline + (size_t)(ff * 8 + j - 1) * U_);
                ulonglong2 wa = *(const ulonglong2*)(wrow + cg * 8);
                ulonglong2 wb = *(const ulonglong2*)(wrow + cg * 8 + 4);
                const ull* fp = (const ull*)&featsd[p][j][0];
#pragma unroll
                for (int rr = 0; rr < 8; rr++) {
                    ull v = fp[rg * 8 + rr];
                    acc[rr][0] = ff2(v, wa.x, acc[rr][0]);
                    acc[rr][1] = ff2(v, wa.y, acc[rr][1]);
                    acc[rr][2] = ff2(v, wb.x, acc[rr][2]);
                    acc[rr][3] = ff2(v, wb.y, acc[rr][3]);
                }
            }
        }
    }
#pragma unroll
    for (int rr = 0; rr < 8; rr++) {
        int b = rg * 8 + rr;
        size_t base = (size_t)cta * (B_ * U_) + b * U_ + cg * 8;
#pragma unroll
        for (int cp = 0; cp < 4; cp++) {
            float lo, hi;
            unpack2(acc[rr][cp], lo, hi);
            *(float2*)&g_part[base + 2 * cp] = make_float2(lo, hi);
        }
    }
}

// ---------------------------------------------------------------------------
// K2b: skip = sig @ skip_w, k-split with atomics.
// ---------------------------------------------------------------------------
__global__ void __launch_bounds__(128) skip_kernel(const float* __restrict__ skip_w) {
    int cta = blockIdx.x;           // 0..129
    int f0 = cta * 32;
    int u = threadIdx.x;
    __shared__ float sig_s[32][65];
    for (int idx = u; idx < 64 * 32; idx += 128) {
        int bb = idx >> 5, fl = idx & 31;
        sig_s[fl][bb] = g_sig[(size_t)bb * SIGD_ + f0 + fl];
    }
    __syncthreads();
    float acc[64];
#pragma unroll
    for (int b = 0; b < 64; b++) acc[b] = 0.0f;
    for (int f = 0; f < 32; f++) {
        float w = skip_w[(size_t)(f0 + f) * U_ + u];
#pragma unroll
        for (int b = 0; b < 64; b++)
            acc[b] = fmaf(sig_s[f][b], w, acc[b]);
    }
#pragma unroll
    for (int b = 0; b < 64; b++) atomicAdd(&g_skip[b * U_ + u], acc[b]);
}

// ---------------------------------------------------------------------------
// K3: reduce h1 partials -> features of h1 (silu + 8 bases).
// ---------------------------------------------------------------------------
__global__ void __launch_bounds__(128) reduce_feat_kernel() {
    int b = blockIdx.x;
    int u = threadIdx.x;
    float h1 = 0.0f;
#pragma unroll 4
    for (int c = 0; c < NCHUNK_; c++)
        h1 += g_part[((size_t)c * B_ + b) * U_ + u];
    g_feat1[((size_t)b * 9 + 0) * U_ + u] = silu_f(h1);
    float bsv[8];
    bspline8(h1, bsv);
#pragma unroll
    for (int j = 0; j < 8; j++)
        g_feat1[((size_t)b * 9 + 1 + j) * U_ + u] = bsv[j];
}

// ---------------------------------------------------------------------------
// K4: h2 partials (k-split over features of layer 2), atomics into g_h2.
// 32 CTAs x 4 features each.
// ---------------------------------------------------------------------------
__global__ void __launch_bounds__(128) h2_kernel(const float* __restrict__ g2_base,
                                                 const float* __restrict__ g2_spline) {
    int f0 = blockIdx.x * 4;
    int u = threadIdx.x;
    __shared__ float fk[9][4][64];
    for (int idx = u; idx < 9 * 4 * 64; idx += 128) {
        int j = idx >> 8, r = idx & 255;
        int fl = r >> 6, bb = r & 63;
        fk[j][fl][bb] = g_feat1[((size_t)bb * 9 + j) * U_ + f0 + fl];
    }
    __syncthreads();
    float acc[64];
#pragma unroll
    for (int b = 0; b < 64; b++) acc[b] = 0.0f;
#pragma unroll
    for (int fl = 0; fl < 4; fl++) {
#pragma unroll
        for (int j = 0; j < 9; j++) {
            float w = (j == 0) ? g2_base[(size_t)(f0 + fl) * U_ + u]
                               : g2_spline[(size_t)((f0 + fl) * 8 + j - 1) * U_ + u];
#pragma unroll
            for (int b = 0; b < 64; b++)
                acc[b] = fmaf(fk[j][fl][b], w, acc[b]);
        }
    }
#pragma unroll
    for (int b = 0; b < 64; b++) atomicAdd(&g_h2[b * U_ + u], acc[b]);
}

// ---------------------------------------------------------------------------
// K5: gate + layernorm + softmax -> g_weights
// ---------------------------------------------------------------------------
__global__ void __launch_bounds__(128) tail_kernel(const float* __restrict__ skip_b,
                                                   const float* __restrict__ gate_ws,
                                                   const float* __restrict__ gate_bs,
                                                   const float* __restrict__ gate_wv,
                                                   const float* __restrict__ gate_bv,
                                                   const float* __restrict__ ln_g,
                                                   const float* __restrict__ ln_b) {
    int b = blockIdx.x;
    int u = threadIdx.x;
    __shared__ float s_h2[128];
    __shared__ float red[16];

    s_h2[u] = g_h2[b * U_ + u];
    __syncthreads();

    float gs = gate_bs[u], gv = gate_bv[u];
#pragma unroll 4
    for (int f = 0; f < 128; f++) {
        float h = s_h2[f];
        gs = fmaf(h, gate_ws[(size_t)f * U_ + u], gs);
        gv = fmaf(h, gate_wv[(size_t)f * U_ + u], gv);
    }
    float pre = g_skip[b * U_ + u] + skip_b[u] +
                (1.0f / (1.0f + __expf(-gs))) * gv;

    // layernorm (eps = 1e-3)
    float v1 = pre, v2 = pre * pre;
#pragma unroll
    for (int o = 16; o; o >>= 1) {
        v1 += __shfl_xor_sync(0xffffffffu, v1, o);
        v2 += __shfl_xor_sync(0xffffffffu, v2, o);
    }
    int w = u >> 5, l = u & 31;
    if (l == 0) { red[w] = v1; red[4 + w] = v2; }
    __syncthreads();
    float mean = (red[0] + red[1] + red[2] + red[3]) * (1.0f / 128.0f);
    float ms   = (red[4] + red[5] + red[6] + red[7]) * (1.0f / 128.0f);
    float var  = ms - mean * mean;
    float ln   = ln_g[u] * (pre - mean) * rsqrtf(var + 1e-3f) + ln_b[u];

    // softmax
    float m = ln;
#pragma unroll
    for (int o = 16; o; o >>= 1) m = fmaxf(m, __shfl_xor_sync(0xffffffffu, m, o));
    if (l == 0) red[8 + w] = m;
    __syncthreads();
    m = fmaxf(fmaxf(red[8], red[9]), fmaxf(red[10], red[11]));
    float e = __expf(ln - m);
    float se = e;
#pragma unroll
    for (int o = 16; o; o >>= 1) se += __shfl_xor_sync(0xffffffffu, se, o);
    if (l == 0) red[12 + w] = se;
    __syncthreads();
    se = red[12] + red[13] + red[14] + red[15];

    g_weights[b * U_ + u] = e / se;
}

// ---------------------------------------------------------------------------
// K6: main fused KAN layer, column-pair f32x2 scheme.
// CTA = 64 rows (one batch, contiguous s) x 128 cols. 128 threads:
//   cg = tid&15 -> cols cg*8..cg*8+7 (4 b64 pairs), rg = tid>>4 -> 8 rows.
// Per (f,j): 2x LDG.128 weights (natural b64 pairs) + 8x (LDS.64 dup'd
// feature + 4 FFMA2). 42 instr / 64 MAC.
// ---------------------------------------------------------------------------
__global__ void __launch_bounds__(128) main_kernel(const float* __restrict__ x,
                                                   const float* __restrict__ tw,
                                                   const float* __restrict__ kan_base,
                                                   const float* __restrict__ kan_spline,
                                                   float* __restrict__ out) {
    int cta = blockIdx.x;            // 1024 CTAs
    int b = cta >> 4;
    int s0 = (cta & 15) << 6;
    int tid = threadIdx.x;
    int cg = tid & 15, rg = tid >> 4;
    __shared__ float xt[64 * 65];    // padded
    __shared__ float2 featsd[2][9][64];

    for (int idx = tid; idx < 64 * 64; idx += 128) {
        int r = idx >> 6, d = idx & 63;
        xt[r * 65 + d] = tw[s0 + r] * x[(size_t)(b * S_ + s0 + r) * D_ + d];
    }

    ull acc[8][4];
#pragma unroll
    for (int r = 0; r < 8; r++)
#pragma unroll
        for (int c = 0; c < 4; c++) acc[r][c] = 0ull;

    for (int f = 0; f < 64; f += 2) {
        __syncthreads();   // xt ready (f=0) / featsd reuse
        {
            int p = tid >> 6, r = tid & 63;
            float v = xt[r * 65 + f + p];
            float sv = silu_f(v);
            featsd[p][0][r] = make_float2(sv, sv);
            float bsv[8];
            bspline8(v, bsv);
#pragma unroll
            for (int j = 0; j < 8; j++)
                featsd[p][1 + j][r] = make_float2(bsv[j], bsv[j]);
        }
        __syncthreads();
#pragma unroll
        for (int p = 0; p < 2; p++) {
            int ff = f + p;
#pragma unroll
            for (int j = 0; j < 9; j++) {
                const float* wrow = (j == 0) ? (kan_base + (size_t)ff * U_)
                                             : (kan_spline + (size_t)(ff * 8 + j - 1) * U_);
                ulonglong2 wa = *(const ulonglong2*)(wrow + cg * 8);
                ulonglong2 wb = *(const ulonglong2*)(wrow + cg * 8 + 4);
                const ull* fp = (const ull*)&featsd[p][j][0];
#pragma unroll
                for (int rr = 0; rr < 8; rr++) {
                    ull v = fp[rg * 8 + rr];
                    acc[rr][0] = ff2(v, wa.x, acc[rr][0]);
                    acc[rr][1] = ff2(v, wa.y, acc[rr][1]);
                    acc[rr][2] = ff2(v, wb.x, acc[rr][2]);
                    acc[rr][3] = ff2(v, wb.y, acc[rr][3]);
                }
            }
        }
    }

    float4 wv0 = *(const float4*)&g_weights[b * U_ + cg * 8];
    float4 wv1 = *(const float4*)&g_weights[b * U_ + cg * 8 + 4];
#pragma unroll
    for (int rr = 0; rr < 8; rr++) {
        int row = rg * 8 + rr;
        float o[8];
        unpack2(acc[rr][0], o[0], o[1]);
        unpack2(acc[rr][1], o[2], o[3]);
        unpack2(acc[rr][2], o[4], o[5]);
        unpack2(acc[rr][3], o[6], o[7]);
        float4 r0 = make_float4(o[0] * wv0.x, o[1] * wv0.y, o[2] * wv0.z, o[3] * wv0.w);
        float4 r1 = make_float4(o[4] * wv1.x, o[5] * wv1.y, o[6] * wv1.z, o[7] * wv1.w);
        size_t obase = (size_t)(b * S_ + s0 + row) * U_ + cg * 8;
        *(float4*)&out[obase] = r0;
        *(float4*)&out[obase + 4] = r1;
    }
}

// ---------------------------------------------------------------------------
extern "C" void kernel_launch(void* const* d_in, const int* in_sizes, int n_in,
                              void* d_out, int out_size) {
    const float* x          = (const float*)d_in[0];
    const float* tw         = (const float*)d_in[1];
    const float* kan_base   = (const float*)d_in[2];
    const float* kan_spline = (const float*)d_in[3];
    const float* g1_base    = (const float*)d_in[4];
    const float* g1_spline  = (const float*)d_in[5];
    const float* g2_base    = (const float*)d_in[6];
    const float* g2_spline  = (const float*)d_in[7];
    const float* skip_w     = (const float*)d_in[8];
    const float* skip_b     = (const float*)d_in[9];
    const float* gate_ws    = (const float*)d_in[10];
    const float* gate_bs    = (const float*)d_in[11];
    const float* gate_wv    = (const float*)d_in[12];
    const float* gate_bv    = (const float*)d_in[13];
    const float* ln_g       = (const float*)d_in[14];
    const float* ln_b       = (const float*)d_in[15];
    float* out = (float*)d_out;

    zero_kernel<<<(ZTOT_ + 255) / 256, 256>>>();
    sig_kernel<<<dim3(B_, 8), 256>>>(x, tw);
    grkan1_kernel<<<NCHUNK_, 128>>>(g1_base, g1_spline);
    skip_kernel<<<NCHUNK_, 128>>>(skip_w);
    reduce_feat_kernel<<<B_, 128>>>();
    h2_kernel<<<32, 128>>>(g2_base, g2_spline);
    tail_kernel<<<B_, 128>>>(skip_b, gate_ws, gate_bs, gate_wv, gate_bv, ln_g, ln_b);
    main_kernel<<<1024, 128>>>(x, tw, kan_base, kan_spline, out);
}

// round 8
// speedup vs baseline: 2.5231x; 1.5247x over previous
#include <cuda_runtime.h>
#include <cuda_bf16.h>

// ---------------------------------------------------------------------------
// SigTKANDense: tw*x -> depth-2 signature -> GRKAN (softmax weights) ->
//               big KAN-linear over (B*S) rows -> scale by weights.
// B=64, S=1024, D=64, U=128, NB=8, SIG_DIM=4160.
// Main GEMMs now on tensor cores via tf32 mma.sync (m16n8k8).
// ---------------------------------------------------------------------------

#define B_ 64
#define S_ 1024
#define D_ 64
#define U_ 128
#define SIGD_ 4160
#define NCHUNK_ 130   // 4160/32 feature chunks

typedef unsigned long long ull;

// scratch (no allocations allowed -> device globals)
__device__ float g_sig[B_ * SIGD_];            // [b][4160]
__device__ float g_part[NCHUNK_ * B_ * U_];    // h1 partials [chunk][b][u]
__device__ float g_skip[B_ * U_];              // skip accumulator (atomics)
__device__ float g_h2[B_ * U_];                // h2 accumulator (atomics)
__device__ float g_feat1[B_ * 9 * U_];         // features of h1: [b][j][u]
__device__ float g_weights[B_ * U_];           // softmax weights per batch

// ---------------------------------------------------------------------------
// cubic B-spline, 12 uniform knots, 8 bases out
// ---------------------------------------------------------------------------
__device__ __forceinline__ void bspline8(float x, float* bs) {
    float b[11];
#pragma unroll
    for (int i = 0; i < 11; i++) {
        float g0 = (float)((i - 3) * 0.4 - 1.0);
        float g1 = (float)((i - 2) * 0.4 - 1.0);
        b[i] = (x >= g0 && x < g1) ? 1.0f : 0.0f;
    }
#pragma unroll
    for (int p = 1; p <= 3; p++) {
        float inv = (float)(1.0 / (0.4 * p));
#pragma unroll
        for (int i = 0; i < 11 - p; i++) {
            float gi  = (float)((i - 3) * 0.4 - 1.0);       // grid[i]
            float gip = (float)((i + p - 2) * 0.4 - 1.0);   // grid[i+p+1]
            b[i] = ((x - gi) * b[i] + (gip - x) * b[i + 1]) * inv;
        }
    }
#pragma unroll
    for (int j = 0; j < 8; j++) bs[j] = b[j];
}

__device__ __forceinline__ float silu_f(float x) {
    return x * (1.0f / (1.0f + __expf(-x)));
}

__device__ __forceinline__ unsigned cvt_tf32(float x) {
    unsigned r;
    asm("cvt.rna.tf32.f32 %0, %1;" : "=r"(r) : "f"(x));
    return r;
}

__device__ __forceinline__ void mma_tf32(float d[4],
                                         unsigned a0, unsigned a1,
                                         unsigned a2, unsigned a3,
                                         unsigned b0, unsigned b1) {
    asm("mma.sync.aligned.m16n8k8.row.col.f32.tf32.tf32.f32 "
        "{%0,%1,%2,%3},{%4,%5,%6,%7},{%8,%9},{%0,%1,%2,%3};"
        : "+f"(d[0]), "+f"(d[1]), "+f"(d[2]), "+f"(d[3])
        : "r"(a0), "r"(a1), "r"(a2), "r"(a3), "r"(b0), "r"(b1));
}

#define SFA_STRIDE 76    // sfeat row stride (conflict-free for A frags)
#define SWB_STRIDE 136   // weight row stride (conflict-free for B frags)

extern __shared__ float dynsm[];

// ---------------------------------------------------------------------------
// K0: zero the accumulators (g_sig, g_skip, g_h2)
// ---------------------------------------------------------------------------
#define ZTOT_ (B_ * SIGD_ + 2 * B_ * U_)
__global__ void zero_kernel() {
    int i = blockIdx.x * blockDim.x + threadIdx.x;
    if (i < B_ * SIGD_) g_sig[i] = 0.0f;
    else if (i < B_ * SIGD_ + B_ * U_) g_skip[i - B_ * SIGD_] = 0.0f;
    else if (i < ZTOT_) g_h2[i - B_ * SIGD_ - B_ * U_] = 0.0f;
}

// ---------------------------------------------------------------------------
// K1: depth-2 signature (unchanged).
// ---------------------------------------------------------------------------
__global__ void __launch_bounds__(256) sig_kernel(const float* __restrict__ x,
                                                  const float* __restrict__ tw) {
    int b = blockIdx.x;
    int chunk = blockIdx.y;
    int t0 = chunk * 128;
    int t1 = min(1023, t0 + 128);
    int nt = t1 - t0;
    __shared__ float rows[129 * 64];
    __shared__ float w0s[64];
    __shared__ float cu[2048];
    int tid = threadIdx.x;

    if (tid < 64) w0s[tid] = tw[0] * x[(size_t)(b * S_) * D_ + tid];
    for (int idx = tid; idx < (nt + 1) * 64; idx += 256) {
        int r = idx >> 6, d = idx & 63;
        rows[idx] = tw[t0 + r] * x[(size_t)(b * S_ + t0 + r) * D_ + d];
    }
    __syncthreads();

    float acc[4][4];
#pragma unroll
    for (int a = 0; a < 4; a++)
#pragma unroll
        for (int e = 0; e < 4; e++) acc[a][e] = 0.0f;

    int tj = (tid & 15) * 4;
    int ti = (tid >> 4) * 4;

    for (int tb = 0; tb < nt; tb += 16) {
        int m = min(16, nt - tb);
        for (int idx = tid; idx < m * 64; idx += 256) {
            int lt = idx >> 6, d = idx & 63;
            float r0 = rows[(tb + lt) * 64 + d];
            float r1 = rows[(tb + lt + 1) * 64 + d];
            cu[lt * 64 + d] = 0.5f * (r0 + r1) - w0s[d];
            cu[1024 + lt * 64 + d] = r1 - r0;
        }
        __syncthreads();
        for (int lt = 0; lt < m; lt++) {
            float4 ci = *(const float4*)&cu[lt * 64 + ti];
            float4 uj = *(const float4*)&cu[1024 + lt * 64 + tj];
            float c[4] = {ci.x, ci.y, ci.z, ci.w};
            float u[4] = {uj.x, uj.y, uj.z, uj.w};
#pragma unroll
            for (int a = 0; a < 4; a++)
#pragma unroll
                for (int e = 0; e < 4; e++) acc[a][e] = fmaf(c[a], u[e], acc[a][e]);
        }
        __syncthreads();
    }

    float* s2 = g_sig + (size_t)b * SIGD_ + 64;
#pragma unroll
    for (int a = 0; a < 4; a++)
#pragma unroll
        for (int e = 0; e < 4; e++)
            atomicAdd(&s2[(ti + a) * 64 + (tj + e)], acc[a][e]);

    if (chunk == 0 && tid < 64) {
        g_sig[(size_t)b * SIGD_ + tid] =
            tw[1023] * x[(size_t)(b * S_ + 1023) * D_ + tid] - w0s[tid];
    }
}

// ---------------------------------------------------------------------------
// K2: GRKAN stage-1 h1 partials via tf32 mma.
// CTA = 32 features (K-chunk 288) x M=64 batches x N=128.
// 128 threads = 4 warps, warp w -> batch rows w*16..w*16+15.
// 4 sub-chunks of 8 features (72 k each): produce features (tf32) into
// sfeat[64][76], stage weights (tf32) into swb[72][136], mma 9 ksteps x 16 nt.
// ---------------------------------------------------------------------------
__global__ void __launch_bounds__(128) grkan1_kernel(const float* __restrict__ g1_base,
                                                     const float* __restrict__ g1_spline) {
    int cta = blockIdx.x;           // 0..129
    int f0 = cta * 32;
    int tid = threadIdx.x;
    int lane = tid & 31, warp = tid >> 5;
    int gid = lane >> 2, tg = lane & 3;
    float* sfeat = dynsm;                       // [64][SFA_STRIDE]
    float* swb = dynsm + 64 * SFA_STRIDE;       // [72][SWB_STRIDE]
    __shared__ float sig_s[64][33];

    for (int idx = tid; idx < 64 * 32; idx += 128) {
        int bb = idx >> 5, fl = idx & 31;
        sig_s[bb][fl] = g_sig[(size_t)bb * SIGD_ + f0 + fl];
    }

    float d[16][4];
#pragma unroll
    for (int n = 0; n < 16; n++)
#pragma unroll
        for (int c = 0; c < 4; c++) d[n][c] = 0.0f;

    for (int sc = 0; sc < 4; sc++) {
        __syncthreads();
        // produce features: 64 rows x 8 features
#pragma unroll
        for (int t = 0; t < 4; t++) {
            int task = tid + t * 128;
            int row = task >> 3, fg = task & 7;
            float v = sig_s[row][sc * 8 + fg];
            unsigned* fp = (unsigned*)&sfeat[row * SFA_STRIDE + fg * 9];
            fp[0] = cvt_tf32(silu_f(v));
            float bs[8];
            bspline8(v, bs);
#pragma unroll
            for (int j = 0; j < 8; j++) fp[1 + j] = cvt_tf32(bs[j]);
        }
        // stage weights: rows kl=fl*9+jj (72), cols u (128)
#pragma unroll 4
        for (int kl = 0; kl < 72; kl++) {
            int fl = kl / 9, jj = kl - fl * 9;
            int f = f0 + sc * 8 + fl;
            float w = (jj == 0) ? g1_base[(size_t)f * U_ + tid]
                                : g1_spline[(size_t)(f * 8 + jj - 1) * U_ + tid];
            ((unsigned*)swb)[kl * SWB_STRIDE + tid] = cvt_tf32(w);
        }
        __syncthreads();
        int m0 = warp * 16;
        const unsigned* sa = (const unsigned*)sfeat;
        const unsigned* sb = (const unsigned*)swb;
#pragma unroll
        for (int kk = 0; kk < 9; kk++) {
            int kl = kk * 8;
            unsigned a0 = sa[(m0 + gid) * SFA_STRIDE + kl + tg];
            unsigned a1 = sa[(m0 + gid + 8) * SFA_STRIDE + kl + tg];
            unsigned a2 = sa[(m0 + gid) * SFA_STRIDE + kl + tg + 4];
            unsigned a3 = sa[(m0 + gid + 8) * SFA_STRIDE + kl + tg + 4];
#pragma unroll
            for (int ntile = 0; ntile < 16; ntile++) {
                unsigned b0 = sb[(kl + tg) * SWB_STRIDE + ntile * 8 + gid];
                unsigned b1 = sb[(kl + tg + 4) * SWB_STRIDE + ntile * 8 + gid];
                mma_tf32(d[ntile], a0, a1, a2, a3, b0, b1);
            }
        }
    }
    // epilogue: partial h1 -> g_part[cta][b][u]
    int b0r = warp * 16 + gid;
#pragma unroll
    for (int ntile = 0; ntile < 16; ntile++) {
        int c0 = ntile * 8 + tg * 2;
        size_t base = (size_t)cta * (B_ * U_);
        *(float2*)&g_part[base + b0r * U_ + c0] = make_float2(d[ntile][0], d[ntile][1]);
        *(float2*)&g_part[base + (b0r + 8) * U_ + c0] = make_float2(d[ntile][2], d[ntile][3]);
    }
}

// ---------------------------------------------------------------------------
// K2b: skip = sig @ skip_w, k-split with atomics. 512 threads, acc[16].
// ---------------------------------------------------------------------------
__global__ void __launch_bounds__(512) skip_kernel(const float* __restrict__ skip_w) {
    int cta = blockIdx.x;           // 0..129
    int f0 = cta * 32;
    int tid = threadIdx.x;
    int u = tid & 127, bh = tid >> 7;    // 4 batch groups of 16
    __shared__ float sig_s[32][65];
    for (int idx = tid; idx < 64 * 32; idx += 512) {
        int bb = idx >> 5, fl = idx & 31;
        sig_s[fl][bb] = g_sig[(size_t)bb * SIGD_ + f0 + fl];
    }
    __syncthreads();
    float acc[16];
#pragma unroll
    for (int b = 0; b < 16; b++) acc[b] = 0.0f;
    for (int f = 0; f < 32; f++) {
        float w = skip_w[(size_t)(f0 + f) * U_ + u];
        const float* sp = &sig_s[f][bh * 16];
#pragma unroll
        for (int b = 0; b < 16; b++)
            acc[b] = fmaf(sp[b], w, acc[b]);
    }
#pragma unroll
    for (int b = 0; b < 16; b++)
        atomicAdd(&g_skip[(bh * 16 + b) * U_ + u], acc[b]);
}

// ---------------------------------------------------------------------------
// K3: reduce h1 partials -> features of h1 (silu + 8 bases).
// ---------------------------------------------------------------------------
__global__ void __launch_bounds__(128) reduce_feat_kernel() {
    int b = blockIdx.x;
    int u = threadIdx.x;
    float h1 = 0.0f;
#pragma unroll 4
    for (int c = 0; c < NCHUNK_; c++)
        h1 += g_part[((size_t)c * B_ + b) * U_ + u];
    g_feat1[((size_t)b * 9 + 0) * U_ + u] = silu_f(h1);
    float bsv[8];
    bspline8(h1, bsv);
#pragma unroll
    for (int j = 0; j < 8; j++)
        g_feat1[((size_t)b * 9 + 1 + j) * U_ + u] = bsv[j];
}

// ---------------------------------------------------------------------------
// K4: h2 partials (k-split over features of layer 2), atomics into g_h2.
// ---------------------------------------------------------------------------
__global__ void __launch_bounds__(128) h2_kernel(const float* __restrict__ g2_base,
                                                 const float* __restrict__ g2_spline) {
    int f0 = blockIdx.x * 4;
    int u = threadIdx.x;
    __shared__ float fk[9][4][64];
    for (int idx = u; idx < 9 * 4 * 64; idx += 128) {
        int j = idx >> 8, r = idx & 255;
        int fl = r >> 6, bb = r & 63;
        fk[j][fl][bb] = g_feat1[((size_t)bb * 9 + j) * U_ + f0 + fl];
    }
    __syncthreads();
    float acc[64];
#pragma unroll
    for (int b = 0; b < 64; b++) acc[b] = 0.0f;
#pragma unroll
    for (int fl = 0; fl < 4; fl++) {
#pragma unroll
        for (int j = 0; j < 9; j++) {
            float w = (j == 0) ? g2_base[(size_t)(f0 + fl) * U_ + u]
                               : g2_spline[(size_t)((f0 + fl) * 8 + j - 1) * U_ + u];
#pragma unroll
            for (int b = 0; b < 64; b++)
                acc[b] = fmaf(fk[j][fl][b], w, acc[b]);
        }
    }
#pragma unroll
    for (int b = 0; b < 64; b++) atomicAdd(&g_h2[b * U_ + u], acc[b]);
}

// ---------------------------------------------------------------------------
// K5: gate + layernorm + softmax -> g_weights
// ---------------------------------------------------------------------------
__global__ void __launch_bounds__(128) tail_kernel(const float* __restrict__ skip_b,
                                                   const float* __restrict__ gate_ws,
                                                   const float* __restrict__ gate_bs,
                                                   const float* __restrict__ gate_wv,
                                                   const float* __restrict__ gate_bv,
                                                   const float* __restrict__ ln_g,
                                                   const float* __restrict__ ln_b) {
    int b = blockIdx.x;
    int u = threadIdx.x;
    __shared__ float s_h2[128];
    __shared__ float red[16];

    s_h2[u] = g_h2[b * U_ + u];
    __syncthreads();

    float gs = gate_bs[u], gv = gate_bv[u];
#pragma unroll 4
    for (int f = 0; f < 128; f++) {
        float h = s_h2[f];
        gs = fmaf(h, gate_ws[(size_t)f * U_ + u], gs);
        gv = fmaf(h, gate_wv[(size_t)f * U_ + u], gv);
    }
    float pre = g_skip[b * U_ + u] + skip_b[u] +
                (1.0f / (1.0f + __expf(-gs))) * gv;

    float v1 = pre, v2 = pre * pre;
#pragma unroll
    for (int o = 16; o; o >>= 1) {
        v1 += __shfl_xor_sync(0xffffffffu, v1, o);
        v2 += __shfl_xor_sync(0xffffffffu, v2, o);
    }
    int w = u >> 5, l = u & 31;
    if (l == 0) { red[w] = v1; red[4 + w] = v2; }
    __syncthreads();
    float mean = (red[0] + red[1] + red[2] + red[3]) * (1.0f / 128.0f);
    float ms   = (red[4] + red[5] + red[6] + red[7]) * (1.0f / 128.0f);
    float var  = ms - mean * mean;
    float ln   = ln_g[u] * (pre - mean) * rsqrtf(var + 1e-3f) + ln_b[u];

    float m = ln;
#pragma unroll
    for (int o = 16; o; o >>= 1) m = fmaxf(m, __shfl_xor_sync(0xffffffffu, m, o));
    if (l == 0) red[8 + w] = m;
    __syncthreads();
    m = fmaxf(fmaxf(red[8], red[9]), fmaxf(red[10], red[11]));
    float e = __expf(ln - m);
    float se = e;
#pragma unroll
    for (int o = 16; o; o >>= 1) se += __shfl_xor_sync(0xffffffffu, se, o);
    if (l == 0) red[12 + w] = se;
    __syncthreads();
    se = red[12] + red[13] + red[14] + red[15];

    g_weights[b * U_ + u] = e / se;
}

// ---------------------------------------------------------------------------
// K6: main fused KAN layer via tf32 mma.
// CTA = 128 rows (one batch, contiguous s) x 128 cols, K=576.
// 256 threads = 8 warps; warp w -> rows w*16..w*16+15.
// 8 chunks of 8 input features (72 k each): produce spline features (tf32)
// into sfeat[128][76], stage weights into swb[72][136], 9 ksteps x 16 ntiles.
// ---------------------------------------------------------------------------
__global__ void __launch_bounds__(256) main_kernel(const float* __restrict__ x,
                                                   const float* __restrict__ tw,
                                                   const float* __restrict__ kan_base,
                                                   const float* __restrict__ kan_spline,
                                                   float* __restrict__ out) {
    int cta = blockIdx.x;            // 512 CTAs
    int b = cta >> 3;
    int s0 = (cta & 7) << 7;         // 128 rows per CTA
    int tid = threadIdx.x;
    int lane = tid & 31, warp = tid >> 5;
    int gid = lane >> 2, tg = lane & 3;
    float* sfeat = dynsm;                        // [128][SFA_STRIDE]
    float* swb = dynsm + 128 * SFA_STRIDE;       // [72][SWB_STRIDE]

    float d[16][4];
#pragma unroll
    for (int n = 0; n < 16; n++)
#pragma unroll
        for (int c = 0; c < 4; c++) d[n][c] = 0.0f;

    for (int fc = 0; fc < 8; fc++) {
        __syncthreads();
        // produce features: 128 rows x 8 features = 1024 tasks
#pragma unroll
        for (int t = 0; t < 4; t++) {
            int task = tid + t * 256;
            int row = task >> 3, fg = task & 7;
            int f = fc * 8 + fg;
            float v = tw[s0 + row] * x[(size_t)(b * S_ + s0 + row) * D_ + f];
            unsigned* fp = (unsigned*)&sfeat[row * SFA_STRIDE + fg * 9];
            fp[0] = cvt_tf32(silu_f(v));
            float bs[8];
            bspline8(v, bs);
#pragma unroll
            for (int j = 0; j < 8; j++) fp[1 + j] = cvt_tf32(bs[j]);
        }
        // stage weights: 72 k-rows x 128 u
#pragma unroll 4
        for (int t = 0; t < 36; t++) {
            int idx = tid + t * 256;
            int kl = idx >> 7, u = idx & 127;
            int fl = kl / 9, jj = kl - fl * 9;
            int f = fc * 8 + fl;
            float w = (jj == 0) ? kan_base[(size_t)f * U_ + u]
                                : kan_spline[(size_t)(f * 8 + jj - 1) * U_ + u];
            ((unsigned*)swb)[kl * SWB_STRIDE + u] = cvt_tf32(w);
        }
        __syncthreads();
        int m0 = warp * 16;
        const unsigned* sa = (const unsigned*)sfeat;
        const unsigned* sb = (const unsigned*)swb;
#pragma unroll
        for (int kk = 0; kk < 9; kk++) {
            int kl = kk * 8;
            unsigned a0 = sa[(m0 + gid) * SFA_STRIDE + kl + tg];
            unsigned a1 = sa[(m0 + gid + 8) * SFA_STRIDE + kl + tg];
            unsigned a2 = sa[(m0 + gid) * SFA_STRIDE + kl + tg + 4];
            unsigned a3 = sa[(m0 + gid + 8) * SFA_STRIDE + kl + tg + 4];
#pragma unroll
            for (int ntile = 0; ntile < 16; ntile++) {
                unsigned b0 = sb[(kl + tg) * SWB_STRIDE + ntile * 8 + gid];
                unsigned b1 = sb[(kl + tg + 4) * SWB_STRIDE + ntile * 8 + gid];
                mma_tf32(d[ntile], a0, a1, a2, a3, b0, b1);
            }
        }
    }

    // epilogue: scale by softmax weights and store
    int r0 = s0 + warp * 16 + gid;
#pragma unroll
    for (int ntile = 0; ntile < 16; ntile++) {
        int c0 = ntile * 8 + tg * 2;
        float w0 = g_weights[b * U_ + c0];
        float w1 = g_weights[b * U_ + c0 + 1];
        size_t o0 = (size_t)(b * S_ + r0) * U_ + c0;
        *(float2*)&out[o0] = make_float2(d[ntile][0] * w0, d[ntile][1] * w1);
        size_t o1 = (size_t)(b * S_ + r0 + 8) * U_ + c0;
        *(float2*)&out[o1] = make_float2(d[ntile][2] * w0, d[ntile][3] * w1);
    }
}

// ---------------------------------------------------------------------------
extern "C" void kernel_launch(void* const* d_in, const int* in_sizes, int n_in,
                              void* d_out, int out_size) {
    const float* x          = (const float*)d_in[0];
    const float* tw         = (const float*)d_in[1];
    const float* kan_base   = (const float*)d_in[2];
    const float* kan_spline = (const float*)d_in[3];
    const float* g1_base    = (const float*)d_in[4];
    const float* g1_spline  = (const float*)d_in[5];
    const float* g2_base    = (const float*)d_in[6];
    const float* g2_spline  = (const float*)d_in[7];
    const float* skip_w     = (const float*)d_in[8];
    const float* skip_b     = (const float*)d_in[9];
    const float* gate_ws    = (const float*)d_in[10];
    const float* gate_bs    = (const float*)d_in[11];
    const float* gate_wv    = (const float*)d_in[12];
    const float* gate_bv    = (const float*)d_in[13];
    const float* ln_g       = (const float*)d_in[14];
    const float* ln_b       = (const float*)d_in[15];
    float* out = (float*)d_out;

    const int G1_SMEM = (64 * SFA_STRIDE + 72 * SWB_STRIDE) * 4;     // 58624
    const int MAIN_SMEM = (128 * SFA_STRIDE + 72 * SWB_STRIDE) * 4;  // 78080
    cudaFuncSetAttribute(grkan1_kernel, cudaFuncAttributeMaxDynamicSharedMemorySize, G1_SMEM);
    cudaFuncSetAttribute(main_kernel, cudaFuncAttributeMaxDynamicSharedMemorySize, MAIN_SMEM);

    zero_kernel<<<(ZTOT_ + 255) / 256, 256>>>();
    sig_kernel<<<dim3(B_, 8), 256>>>(x, tw);
    grkan1_kernel<<<NCHUNK_, 128, G1_SMEM>>>(g1_base, g1_spline);
    skip_kernel<<<NCHUNK_, 512>>>(skip_w);
    reduce_feat_kernel<<<B_, 128>>>();
    h2_kernel<<<32, 128>>>(g2_base, g2_spline);
    tail_kernel<<<B_, 128>>>(skip_b, gate_ws, gate_bs, gate_wv, gate_bv, ln_g, ln_b);
    main_kernel<<<512, 256, MAIN_SMEM>>>(x, tw, kan_base, kan_spline, out);
}

// round 9
// speedup vs baseline: 3.8848x; 1.5397x over previous
#include <cuda_runtime.h>
#include <cuda_bf16.h>

// ---------------------------------------------------------------------------
// SigTKANDense: tw*x -> depth-2 signature -> GRKAN (softmax weights) ->
//               big KAN-linear over (B*S) rows -> scale by weights.
// B=64, S=1024, D=64, U=128, NB=8, SIG_DIM=4160.
// tf32 mma.sync (m16n8k8) for big GEMMs; closed-form cubic B-spline.
// ---------------------------------------------------------------------------

#define B_ 64
#define S_ 1024
#define D_ 64
#define U_ 128
#define SIGD_ 4160
#define NCHUNK_ 130   // 4160/32 feature chunks

typedef unsigned long long ull;

// scratch (no allocations allowed -> device globals)
__device__ float    g_sig[B_ * SIGD_];            // [b][4160]
__device__ float    g_part[NCHUNK_ * B_ * U_];    // h1 partials [chunk][b][u]
__device__ float    g_skip[B_ * U_];              // skip accumulator (atomics)
__device__ float    g_h2[B_ * U_];                // h2 accumulator (atomics)
__device__ float    g_feat1[B_ * 9 * U_];         // features of h1: [b][j][u]
__device__ float    g_weights[B_ * U_];           // softmax weights per batch
__device__ unsigned g_wk[576 * U_];               // main KAN weights, tf32 bits, [f*9+j][u]

__device__ __forceinline__ float silu_f(float x) {
    return x * (1.0f / (1.0f + __expf(-x)));
}

__device__ __forceinline__ unsigned cvt_tf32(float x) {
    unsigned r;
    asm("cvt.rna.tf32.f32 %0, %1;" : "=r"(r) : "f"(x));
    return r;
}

// closed-form uniform cubic B-spline: cell index + 4 weights.
// bases j = i, i-1, i-2, i-3 get w0..w3; all others zero.
__device__ __forceinline__ void bspline4(float x, int& i, float* w) {
    float xc = (x + 2.2f) * 2.5f;
    float fi = floorf(xc);
    i = (int)fi;
    float t = xc - fi;
    float t2 = t * t, t3 = t2 * t;
    float omt = 1.0f - t;
    w[0] = t3 * (1.0f / 6.0f);                                   // j = i
    w[1] = (-3.0f * t3 + 3.0f * t2 + 3.0f * t + 1.0f) * (1.0f / 6.0f); // j = i-1
    w[2] = (3.0f * t3 - 6.0f * t2 + 4.0f) * (1.0f / 6.0f);       // j = i-2
    w[3] = omt * omt * omt * (1.0f / 6.0f);                      // j = i-3
}

__device__ __forceinline__ void mma_tf32(float d[4],
                                         unsigned a0, unsigned a1,
                                         unsigned a2, unsigned a3,
                                         unsigned b0, unsigned b1) {
    asm("mma.sync.aligned.m16n8k8.row.col.f32.tf32.tf32.f32 "
        "{%0,%1,%2,%3},{%4,%5,%6,%7},{%8,%9},{%0,%1,%2,%3};"
        : "+f"(d[0]), "+f"(d[1]), "+f"(d[2]), "+f"(d[3])
        : "r"(a0), "r"(a1), "r"(a2), "r"(a3), "r"(b0), "r"(b1));
}

#define SFA_STRIDE 76    // sfeat row stride (conflict-free A frags)
#define SWB_STRIDE 136   // weight row stride (conflict-free B frags)

extern __shared__ float dynsm[];

// ---------------------------------------------------------------------------
// K0: zero the accumulators
// ---------------------------------------------------------------------------
#define ZTOT_ (B_ * SIGD_ + 2 * B_ * U_)
__global__ void zero_kernel() {
    int i = blockIdx.x * blockDim.x + threadIdx.x;
    if (i < B_ * SIGD_) g_sig[i] = 0.0f;
    else if (i < B_ * SIGD_ + B_ * U_) g_skip[i - B_ * SIGD_] = 0.0f;
    else if (i < ZTOT_) g_h2[i - B_ * SIGD_ - B_ * U_] = 0.0f;
}

// ---------------------------------------------------------------------------
// K0b: pre-convert main KAN weights to tf32 bits, layout [f*9+j][u]
// ---------------------------------------------------------------------------
__global__ void preconv_kernel(const float* __restrict__ kan_base,
                               const float* __restrict__ kan_spline) {
    int idx = blockIdx.x * 256 + threadIdx.x;
    if (idx >= 576 * U_) return;
    int k = idx >> 7, u = idx & 127;
    int f = k / 9, jj = k - f * 9;
    float w = (jj == 0) ? kan_base[(size_t)f * U_ + u]
                        : kan_spline[(size_t)(f * 8 + jj - 1) * U_ + u];
    g_wk[idx] = cvt_tf32(w);
}

// ---------------------------------------------------------------------------
// K1: depth-2 signature (fp32 exact; feeds the fp32 skip path).
// ---------------------------------------------------------------------------
__global__ void __launch_bounds__(256) sig_kernel(const float* __restrict__ x,
                                                  const float* __restrict__ tw) {
    int b = blockIdx.x;
    int chunk = blockIdx.y;
    int t0 = chunk * 128;
    int t1 = min(1023, t0 + 128);
    int nt = t1 - t0;
    __shared__ float rows[129 * 64];
    __shared__ float w0s[64];
    __shared__ float cu[2048];
    int tid = threadIdx.x;

    if (tid < 64) w0s[tid] = tw[0] * x[(size_t)(b * S_) * D_ + tid];
    for (int idx = tid; idx < (nt + 1) * 64; idx += 256) {
        int r = idx >> 6, d = idx & 63;
        rows[idx] = tw[t0 + r] * x[(size_t)(b * S_ + t0 + r) * D_ + d];
    }
    __syncthreads();

    float acc[4][4];
#pragma unroll
    for (int a = 0; a < 4; a++)
#pragma unroll
        for (int e = 0; e < 4; e++) acc[a][e] = 0.0f;

    int tj = (tid & 15) * 4;
    int ti = (tid >> 4) * 4;

    for (int tb = 0; tb < nt; tb += 16) {
        int m = min(16, nt - tb);
        for (int idx = tid; idx < m * 64; idx += 256) {
            int lt = idx >> 6, d = idx & 63;
            float r0 = rows[(tb + lt) * 64 + d];
            float r1 = rows[(tb + lt + 1) * 64 + d];
            cu[lt * 64 + d] = 0.5f * (r0 + r1) - w0s[d];
            cu[1024 + lt * 64 + d] = r1 - r0;
        }
        __syncthreads();
        for (int lt = 0; lt < m; lt++) {
            float4 ci = *(const float4*)&cu[lt * 64 + ti];
            float4 uj = *(const float4*)&cu[1024 + lt * 64 + tj];
            float c[4] = {ci.x, ci.y, ci.z, ci.w};
            float u[4] = {uj.x, uj.y, uj.z, uj.w};
#pragma unroll
            for (int a = 0; a < 4; a++)
#pragma unroll
                for (int e = 0; e < 4; e++) acc[a][e] = fmaf(c[a], u[e], acc[a][e]);
        }
        __syncthreads();
    }

    float* s2 = g_sig + (size_t)b * SIGD_ + 64;
#pragma unroll
    for (int a = 0; a < 4; a++)
#pragma unroll
        for (int e = 0; e < 4; e++)
            atomicAdd(&s2[(ti + a) * 64 + (tj + e)], acc[a][e]);

    if (chunk == 0 && tid < 64) {
        g_sig[(size_t)b * SIGD_ + tid] =
            tw[1023] * x[(size_t)(b * S_ + 1023) * D_ + tid] - w0s[tid];
    }
}

// ---------------------------------------------------------------------------
// K2: GRKAN stage-1 h1 partials via tf32 mma. 130 CTAs x 32 features.
// ---------------------------------------------------------------------------
__global__ void __launch_bounds__(128) grkan1_kernel(const float* __restrict__ g1_base,
                                                     const float* __restrict__ g1_spline) {
    int cta = blockIdx.x;           // 0..129
    int f0 = cta * 32;
    int tid = threadIdx.x;
    int lane = tid & 31, warp = tid >> 5;
    int gid = lane >> 2, tg = lane & 3;
    float* sfeat = dynsm;                       // [64][SFA_STRIDE]
    float* swb = dynsm + 64 * SFA_STRIDE;       // [72][SWB_STRIDE]
    __shared__ float sig_s[64][33];

    for (int idx = tid; idx < 64 * 32; idx += 128) {
        int bb = idx >> 5, fl = idx & 31;
        sig_s[bb][fl] = g_sig[(size_t)bb * SIGD_ + f0 + fl];
    }

    float d[16][4];
#pragma unroll
    for (int n = 0; n < 16; n++)
#pragma unroll
        for (int c = 0; c < 4; c++) d[n][c] = 0.0f;

    for (int sc = 0; sc < 4; sc++) {
        __syncthreads();
        // produce features: 64 rows x 8 features = 512 tasks / 128 threads
#pragma unroll
        for (int t = 0; t < 4; t++) {
            int task = tid + t * 128;
            int row = task >> 3, fg = task & 7;
            float v = sig_s[row][sc * 8 + fg];
            unsigned* fp = (unsigned*)&sfeat[row * SFA_STRIDE + fg * 9];
            fp[0] = cvt_tf32(silu_f(v));
#pragma unroll
            for (int j = 1; j <= 8; j++) fp[j] = 0u;
            int ci; float wv[4];
            bspline4(v, ci, wv);
#pragma unroll
            for (int k = 0; k < 4; k++) {
                int j = ci - k;
                if ((unsigned)j < 8u) fp[1 + j] = cvt_tf32(wv[k]);
            }
        }
        // stage weights: 72 rows x 32 float4 = 2304 tasks / 128 threads
#pragma unroll
        for (int t = 0; t < 18; t++) {
            int idx = tid + t * 128;
            int row = idx >> 5, c4 = idx & 31;
            int fl = row / 9, jj = row - fl * 9;
            int f = f0 + sc * 8 + fl;
            const float* src = (jj == 0) ? (g1_base + (size_t)f * U_)
                                         : (g1_spline + (size_t)(f * 8 + jj - 1) * U_);
            float4 v = *(const float4*)(src + c4 * 4);
            unsigned* dst = (unsigned*)swb + row * SWB_STRIDE + c4 * 4;
            dst[0] = cvt_tf32(v.x); dst[1] = cvt_tf32(v.y);
            dst[2] = cvt_tf32(v.z); dst[3] = cvt_tf32(v.w);
        }
        __syncthreads();
        int m0 = warp * 16;
        const unsigned* sa = (const unsigned*)sfeat;
        const unsigned* sb = (const unsigned*)swb;
#pragma unroll
        for (int kk = 0; kk < 9; kk++) {
            int kl = kk * 8;
            unsigned a0 = sa[(m0 + gid) * SFA_STRIDE + kl + tg];
            unsigned a1 = sa[(m0 + gid + 8) * SFA_STRIDE + kl + tg];
            unsigned a2 = sa[(m0 + gid) * SFA_STRIDE + kl + tg + 4];
            unsigned a3 = sa[(m0 + gid + 8) * SFA_STRIDE + kl + tg + 4];
#pragma unroll
            for (int ntile = 0; ntile < 16; ntile++) {
                unsigned b0 = sb[(kl + tg) * SWB_STRIDE + ntile * 8 + gid];
                unsigned b1 = sb[(kl + tg + 4) * SWB_STRIDE + ntile * 8 + gid];
                mma_tf32(d[ntile], a0, a1, a2, a3, b0, b1);
            }
        }
    }
    int b0r = warp * 16 + gid;
#pragma unroll
    for (int ntile = 0; ntile < 16; ntile++) {
        int c0 = ntile * 8 + tg * 2;
        size_t base = (size_t)cta * (B_ * U_);
        *(float2*)&g_part[base + b0r * U_ + c0] = make_float2(d[ntile][0], d[ntile][1]);
        *(float2*)&g_part[base + (b0r + 8) * U_ + c0] = make_float2(d[ntile][2], d[ntile][3]);
    }
}

// ---------------------------------------------------------------------------
// K2b: skip = sig @ skip_w (fp32), weights staged in smem for MLP.
// ---------------------------------------------------------------------------
__global__ void __launch_bounds__(512) skip_kernel(const float* __restrict__ skip_w) {
    int cta = blockIdx.x;           // 0..129
    int f0 = cta * 32;
    int tid = threadIdx.x;
    int u = tid & 127, bh = tid >> 7;    // 4 batch groups of 16
    __shared__ float sig_s[32][65];
    __shared__ float sw[32][128];
    for (int idx = tid; idx < 64 * 32; idx += 512) {
        int bb = idx >> 5, fl = idx & 31;
        sig_s[fl][bb] = g_sig[(size_t)bb * SIGD_ + f0 + fl];
    }
#pragma unroll
    for (int t = 0; t < 8; t++) {
        int idx = tid + t * 512;
        int row = idx >> 7, uu = idx & 127;
        sw[row][uu] = skip_w[(size_t)(f0 + row) * U_ + uu];
    }
    __syncthreads();
    float acc[16];
#pragma unroll
    for (int b = 0; b < 16; b++) acc[b] = 0.0f;
#pragma unroll 4
    for (int f = 0; f < 32; f++) {
        float w = sw[f][u];
        const float* sp = &sig_s[f][bh * 16];
#pragma unroll
        for (int b = 0; b < 16; b++)
            acc[b] = fmaf(sp[b], w, acc[b]);
    }
#pragma unroll
    for (int b = 0; b < 16; b++)
        atomicAdd(&g_skip[(bh * 16 + b) * U_ + u], acc[b]);
}

// ---------------------------------------------------------------------------
// K3: reduce h1 partials (4-way split) -> features of h1.
// ---------------------------------------------------------------------------
__global__ void __launch_bounds__(512) reduce_feat_kernel() {
    int b = blockIdx.x;
    int tid = threadIdx.x;
    int u = tid & 127, cg = tid >> 7;
    __shared__ float red[4][128];
    float h = 0.0f;
#pragma unroll 4
    for (int c = cg; c < NCHUNK_; c += 4)
        h += g_part[((size_t)c * B_ + b) * U_ + u];
    red[cg][u] = h;
    __syncthreads();
    if (tid < 128) {
        float h1 = red[0][u] + red[1][u] + red[2][u] + red[3][u];
        g_feat1[((size_t)b * 9 + 0) * U_ + u] = silu_f(h1);
#pragma unroll
        for (int j = 0; j < 8; j++)
            g_feat1[((size_t)b * 9 + 1 + j) * U_ + u] = 0.0f;
        int ci; float wv[4];
        bspline4(h1, ci, wv);
#pragma unroll
        for (int k = 0; k < 4; k++) {
            int j = ci - k;
            if ((unsigned)j < 8u)
                g_feat1[((size_t)b * 9 + 1 + j) * U_ + u] = wv[k];
        }
    }
}

// ---------------------------------------------------------------------------
// K4: h2 partials (k-split over layer-2 features), atomics into g_h2.
// ---------------------------------------------------------------------------
__global__ void __launch_bounds__(128) h2_kernel(const float* __restrict__ g2_base,
                                                 const float* __restrict__ g2_spline) {
    int f0 = blockIdx.x * 4;
    int u = threadIdx.x;
    __shared__ float fk[9][4][64];
    for (int idx = u; idx < 9 * 4 * 64; idx += 128) {
        int j = idx >> 8, r = idx & 255;
        int fl = r >> 6, bb = r & 63;
        fk[j][fl][bb] = g_feat1[((size_t)bb * 9 + j) * U_ + f0 + fl];
    }
    __syncthreads();
    float acc[64];
#pragma unroll
    for (int b = 0; b < 64; b++) acc[b] = 0.0f;
#pragma unroll
    for (int fl = 0; fl < 4; fl++) {
#pragma unroll
        for (int j = 0; j < 9; j++) {
            float w = (j == 0) ? g2_base[(size_t)(f0 + fl) * U_ + u]
                               : g2_spline[(size_t)((f0 + fl) * 8 + j - 1) * U_ + u];
#pragma unroll
            for (int b = 0; b < 64; b++)
                acc[b] = fmaf(fk[j][fl][b], w, acc[b]);
        }
    }
#pragma unroll
    for (int b = 0; b < 64; b++) atomicAdd(&g_h2[b * U_ + u], acc[b]);
}

// ---------------------------------------------------------------------------
// K5: gate + layernorm + softmax -> g_weights
// ---------------------------------------------------------------------------
__global__ void __launch_bounds__(128) tail_kernel(const float* __restrict__ skip_b,
                                                   const float* __restrict__ gate_ws,
                                                   const float* __restrict__ gate_bs,
                                                   const float* __restrict__ gate_wv,
                                                   const float* __restrict__ gate_bv,
                                                   const float* __restrict__ ln_g,
                                                   const float* __restrict__ ln_b) {
    int b = blockIdx.x;
    int u = threadIdx.x;
    __shared__ float s_h2[128];
    __shared__ float red[16];

    s_h2[u] = g_h2[b * U_ + u];
    __syncthreads();

    float gs = gate_bs[u], gv = gate_bv[u];
#pragma unroll 4
    for (int f = 0; f < 128; f++) {
        float h = s_h2[f];
        gs = fmaf(h, gate_ws[(size_t)f * U_ + u], gs);
        gv = fmaf(h, gate_wv[(size_t)f * U_ + u], gv);
    }
    float pre = g_skip[b * U_ + u] + skip_b[u] +
                (1.0f / (1.0f + __expf(-gs))) * gv;

    float v1 = pre, v2 = pre * pre;
#pragma unroll
    for (int o = 16; o; o >>= 1) {
        v1 += __shfl_xor_sync(0xffffffffu, v1, o);
        v2 += __shfl_xor_sync(0xffffffffu, v2, o);
    }
    int w = u >> 5, l = u & 31;
    if (l == 0) { red[w] = v1; red[4 + w] = v2; }
    __syncthreads();
    float mean = (red[0] + red[1] + red[2] + red[3]) * (1.0f / 128.0f);
    float ms   = (red[4] + red[5] + red[6] + red[7]) * (1.0f / 128.0f);
    float var  = ms - mean * mean;
    float ln   = ln_g[u] * (pre - mean) * rsqrtf(var + 1e-3f) + ln_b[u];

    float m = ln;
#pragma unroll
    for (int o = 16; o; o >>= 1) m = fmaxf(m, __shfl_xor_sync(0xffffffffu, m, o));
    if (l == 0) red[8 + w] = m;
    __syncthreads();
    m = fmaxf(fmaxf(red[8], red[9]), fmaxf(red[10], red[11]));
    float e = __expf(ln - m);
    float se = e;
#pragma unroll
    for (int o = 16; o; o >>= 1) se += __shfl_xor_sync(0xffffffffu, se, o);
    if (l == 0) red[12 + w] = se;
    __syncthreads();
    se = red[12] + red[13] + red[14] + red[15];

    g_weights[b * U_ + u] = e / se;
}

// ---------------------------------------------------------------------------
// K6: main fused KAN layer via tf32 mma, M=32 per warp.
// CTA = 128 rows x 128 cols, K=576; 128 threads = 4 warps (warp -> 32 rows).
// Weights pre-converted (g_wk) and staged via uint4 copies.
// ---------------------------------------------------------------------------
__global__ void __launch_bounds__(128) main_kernel(const float* __restrict__ x,
                                                   const float* __restrict__ tw,
                                                   float* __restrict__ out) {
    int cta = blockIdx.x;            // 512 CTAs
    int b = cta >> 3;
    int s0 = (cta & 7) << 7;         // 128 rows per CTA
    int tid = threadIdx.x;
    int lane = tid & 31, warp = tid >> 5;
    int gid = lane >> 2, tg = lane & 3;
    float* sfeat = dynsm;                        // [128][SFA_STRIDE]
    unsigned* swb = (unsigned*)(dynsm + 128 * SFA_STRIDE);  // [72][SWB_STRIDE]

    float d[2][16][4];
#pragma unroll
    for (int mt = 0; mt < 2; mt++)
#pragma unroll
        for (int n = 0; n < 16; n++)
#pragma unroll
            for (int c = 0; c < 4; c++) d[mt][n][c] = 0.0f;

    for (int fc = 0; fc < 8; fc++) {
        __syncthreads();
        // features: 128 rows x 8 features = 1024 tasks / 128 threads
#pragma unroll
        for (int t = 0; t < 8; t++) {
            int task = tid + t * 128;
            int row = task >> 3, fg = task & 7;
            int f = fc * 8 + fg;
            float v = tw[s0 + row] * x[(size_t)(b * S_ + s0 + row) * D_ + f];
            unsigned* fp = (unsigned*)&sfeat[row * SFA_STRIDE + fg * 9];
            fp[0] = cvt_tf32(silu_f(v));
#pragma unroll
            for (int j = 1; j <= 8; j++) fp[j] = 0u;
            int ci; float wv[4];
            bspline4(v, ci, wv);
#pragma unroll
            for (int k = 0; k < 4; k++) {
                int j = ci - k;
                if ((unsigned)j < 8u) fp[1 + j] = cvt_tf32(wv[k]);
            }
        }
        // stage pre-converted weights: 72 rows x 32 uint4 / 128 threads
        const uint4* wsrc = (const uint4*)(g_wk + fc * 72 * U_);
#pragma unroll
        for (int t = 0; t < 18; t++) {
            int idx = tid + t * 128;
            int row = idx >> 5, c4 = idx & 31;
            *(uint4*)(swb + row * SWB_STRIDE + c4 * 4) = wsrc[row * 32 + c4];
        }
        __syncthreads();
        int m0 = warp * 32;
        const unsigned* sa = (const unsigned*)sfeat;
#pragma unroll
        for (int kk = 0; kk < 9; kk++) {
            int kl = kk * 8;
            unsigned a[2][4];
#pragma unroll
            for (int mt = 0; mt < 2; mt++) {
                int mr = m0 + mt * 16;
                a[mt][0] = sa[(mr + gid) * SFA_STRIDE + kl + tg];
                a[mt][1] = sa[(mr + gid + 8) * SFA_STRIDE + kl + tg];
                a[mt][2] = sa[(mr + gid) * SFA_STRIDE + kl + tg + 4];
                a[mt][3] = sa[(mr + gid + 8) * SFA_STRIDE + kl + tg + 4];
            }
#pragma unroll
            for (int ntile = 0; ntile < 16; ntile++) {
                unsigned b0 = swb[(kl + tg) * SWB_STRIDE + ntile * 8 + gid];
                unsigned b1 = swb[(kl + tg + 4) * SWB_STRIDE + ntile * 8 + gid];
                mma_tf32(d[0][ntile], a[0][0], a[0][1], a[0][2], a[0][3], b0, b1);
                mma_tf32(d[1][ntile], a[1][0], a[1][1], a[1][2], a[1][3], b0, b1);
            }
        }
    }

    // epilogue: scale by softmax weights and store
#pragma unroll
    for (int ntile = 0; ntile < 16; ntile++) {
        int c0 = ntile * 8 + tg * 2;
        float w0 = g_weights[b * U_ + c0];
        float w1 = g_weights[b * U_ + c0 + 1];
#pragma unroll
        for (int mt = 0; mt < 2; mt++) {
            int r0 = s0 + warp * 32 + mt * 16 + gid;
            size_t o0 = (size_t)(b * S_ + r0) * U_ + c0;
            *(float2*)&out[o0] = make_float2(d[mt][ntile][0] * w0, d[mt][ntile][1] * w1);
            size_t o1 = (size_t)(b * S_ + r0 + 8) * U_ + c0;
            *(float2*)&out[o1] = make_float2(d[mt][ntile][2] * w0, d[mt][ntile][3] * w1);
        }
    }
}

// ---------------------------------------------------------------------------
extern "C" void kernel_launch(void* const* d_in, const int* in_sizes, int n_in,
                              void* d_out, int out_size) {
    const float* x          = (const float*)d_in[0];
    const float* tw         = (const float*)d_in[1];
    const float* kan_base   = (const float*)d_in[2];
    const float* kan_spline = (const float*)d_in[3];
    const float* g1_base    = (const float*)d_in[4];
    const float* g1_spline  = (const float*)d_in[5];
    const float* g2_base    = (const float*)d_in[6];
    const float* g2_spline  = (const float*)d_in[7];
    const float* skip_w     = (const float*)d_in[8];
    const float* skip_b     = (const float*)d_in[9];
    const float* gate_ws    = (const float*)d_in[10];
    const float* gate_bs    = (const float*)d_in[11];
    const float* gate_wv    = (const float*)d_in[12];
    const float* gate_bv    = (const float*)d_in[13];
    const float* ln_g       = (const float*)d_in[14];
    const float* ln_b       = (const float*)d_in[15];
    float* out = (float*)d_out;

    const int G1_SMEM = (64 * SFA_STRIDE + 72 * SWB_STRIDE) * 4;     // 58624
    const int MAIN_SMEM = (128 * SFA_STRIDE + 72 * SWB_STRIDE) * 4;  // 78080
    cudaFuncSetAttribute(grkan1_kernel, cudaFuncAttributeMaxDynamicSharedMemorySize, G1_SMEM);
    cudaFuncSetAttribute(main_kernel, cudaFuncAttributeMaxDynamicSharedMemorySize, MAIN_SMEM);

    zero_kernel<<<(ZTOT_ + 255) / 256, 256>>>();
    preconv_kernel<<<(576 * U_ + 255) / 256, 256>>>(kan_base, kan_spline);
    sig_kernel<<<dim3(B_, 8), 256>>>(x, tw);
    grkan1_kernel<<<NCHUNK_, 128, G1_SMEM>>>(g1_base, g1_spline);
    skip_kernel<<<NCHUNK_, 512>>>(skip_w);
    reduce_feat_kernel<<<B_, 512>>>();
    h2_kernel<<<32, 128>>>(g2_base, g2_spline);
    tail_kernel<<<B_, 128>>>(skip_b, gate_ws, gate_bs, gate_wv, gate_bv, ln_g, ln_b);
    main_kernel<<<512, 128, MAIN_SMEM>>>(x, tw, out);
}